// round 9
// baseline (speedup 1.0000x reference)
#include <cuda_runtime.h>
#include <cstdint>

// Problem constants
#define N_ATOM   1024
#define N_TOKEN  256
#define C_S      384
#define C_Z      128
#define C_ATOM   128
#define C_PAIR   16
#define LNEPS    1e-5f

// Scratch (allocation-free rule: __device__ globals)
__device__ int   g_tok[N_ATOM];                       // atom -> token
__device__ float g_y[N_TOKEN * N_TOKEN * C_PAIR];     // 4 MB: LN_z(zij)@W_z per token pair
__device__ float g_u[N_TOKEN * C_ATOM];               // LN_s(s_trunk)@W_s per token

// ---------------------------------------------------------------------------
// K1: recover token index from one-hot rows (one warp per atom)
// ---------------------------------------------------------------------------
__global__ __launch_bounds__(256) void tok_kernel(const float* __restrict__ a2t)
{
    int a    = blockIdx.x * 8 + (threadIdx.x >> 5);
    int lane = threadIdx.x & 31;
    const float* row = a2t + (size_t)a * N_TOKEN;
    int best = 0;
#pragma unroll
    for (int i = 0; i < 8; i++) {
        int t = lane + 32 * i;
        if (row[t] > 0.5f) best = t;
    }
#pragma unroll
    for (int o = 16; o; o >>= 1)
        best = max(best, __shfl_xor_sync(0xffffffffu, best, o));
    if (lane == 0) g_tok[a] = best;
}

// ---------------------------------------------------------------------------
// K2: y[t,m,k] = (LN(zij[t,m,:]) ) @ W_z      (one warp per (t,m) pair)
// Each lane owns 4 channels; W_z rows for those channels live in registers
// (64 regs), so no per-pair smem/W_z re-read. 16-output cross-lane reduction
// via a 4-stage butterfly (15 shfl) + 1 redundancy-fold shfl.
// ---------------------------------------------------------------------------
__global__ __launch_bounds__(256, 2) void y_kernel(
    const float* __restrict__ zij, const float* __restrict__ lnw,
    const float* __restrict__ lnb, const float* __restrict__ Wz)
{
    __shared__ float s_Wz[C_Z * C_PAIR];   // 8 KB, staged once per block
    int tid = threadIdx.x;
    for (int i = tid; i < C_Z * C_PAIR; i += 256) s_Wz[i] = Wz[i];
    __syncthreads();

    int lane = tid & 31;
    int c0   = lane << 2;                  // this lane's first channel

    float wreg[4][16];
#pragma unroll
    for (int j = 0; j < 4; j++)
#pragma unroll
        for (int k = 0; k < 16; k++)
            wreg[j][k] = s_Wz[(c0 + j) * 16 + k];

    float lw0 = lnw[c0], lw1 = lnw[c0 + 1], lw2 = lnw[c0 + 2], lw3 = lnw[c0 + 3];
    float lb0 = lnb[c0], lb1 = lnb[c0 + 1], lb2 = lnb[c0 + 2], lb3 = lnb[c0 + 3];

    int gw = blockIdx.x * 8 + (tid >> 5);
    int nw = gridDim.x * 8;
    const float4* z4 = (const float4*)zij;

    for (int pair = gw; pair < N_TOKEN * N_TOKEN; pair += nw) {
        float4 z = __ldg(z4 + (size_t)pair * 32 + lane);

        float s  = z.x + z.y + z.z + z.w;
        float ss = fmaf(z.x, z.x, fmaf(z.y, z.y, fmaf(z.z, z.z, z.w * z.w)));
#pragma unroll
        for (int o = 16; o; o >>= 1) {
            s  += __shfl_xor_sync(0xffffffffu, s,  o);
            ss += __shfl_xor_sync(0xffffffffu, ss, o);
        }
        float mean = s * (1.0f / 128.0f);
        float var  = ss * (1.0f / 128.0f) - mean * mean;
        float rstd = rsqrtf(var + LNEPS);

        float n0 = fmaf((z.x - mean) * rstd, lw0, lb0);
        float n1 = fmaf((z.y - mean) * rstd, lw1, lb1);
        float n2 = fmaf((z.z - mean) * rstd, lw2, lb2);
        float n3 = fmaf((z.w - mean) * rstd, lw3, lb3);

        float acc[16];
#pragma unroll
        for (int k = 0; k < 16; k++)
            acc[k] = fmaf(n0, wreg[0][k],
                     fmaf(n1, wreg[1][k],
                     fmaf(n2, wreg[2][k], n3 * wreg[3][k])));

        // 16-value butterfly reduction across 32 lanes.
        // After stage with mask m=16>>st, k-bit (3-st) == lane bit (4-st).
#pragma unroll
        for (int st = 0; st < 4; st++) {
            const int m = 16 >> st;
            const int h = 8 >> st;
            bool up = (lane & m) != 0;
#pragma unroll
            for (int j = 0; j < h; j++) {
                float send = up ? acc[j] : acc[j + h];
                float keep = up ? acc[j + h] : acc[j];
                acc[j] = keep + __shfl_xor_sync(0xffffffffu, send, m);
            }
        }
        acc[0] += __shfl_xor_sync(0xffffffffu, acc[0], 1);   // fold lane-bit0 redundancy
        int k = (lane >> 1) & 15;
        if ((lane & 1) == 0)
            g_y[(size_t)pair * C_PAIR + k] = acc[0];
    }
}

// ---------------------------------------------------------------------------
// K3: u[t,:] = LN(s_trunk[t,:]) @ W_s   (2 tokens per 256-thread block)
// ---------------------------------------------------------------------------
__global__ __launch_bounds__(256) void u_kernel(
    const float* __restrict__ s_trunk, const float* __restrict__ lnw,
    const float* __restrict__ lnb, const float* __restrict__ Ws)
{
    __shared__ float sn[2][C_S];
    __shared__ float wred[8][2];
    __shared__ float red[2][2];

    int tid  = threadIdx.x;
    int half = tid >> 7;          // 0/1: which token this half handles
    int ht   = tid & 127;
    int t    = blockIdx.x * 2 + half;

    const float* sr = s_trunk + (size_t)t * C_S;
    float x0 = sr[ht], x1 = sr[ht + 128], x2 = sr[ht + 256];
    float s  = x0 + x1 + x2;
    float ss = fmaf(x0, x0, fmaf(x1, x1, x2 * x2));
#pragma unroll
    for (int o = 16; o; o >>= 1) {
        s  += __shfl_xor_sync(0xffffffffu, s,  o);
        ss += __shfl_xor_sync(0xffffffffu, ss, o);
    }
    int warp = tid >> 5, lane = tid & 31;
    if (lane == 0) { wred[warp][0] = s; wred[warp][1] = ss; }
    __syncthreads();
    if (ht == 0) {
        float S = 0.f, SS = 0.f;
        for (int w = half * 4; w < half * 4 + 4; w++) { S += wred[w][0]; SS += wred[w][1]; }
        float mean = S * (1.0f / 384.0f);
        float var  = SS * (1.0f / 384.0f) - mean * mean;
        red[half][0] = mean;
        red[half][1] = rsqrtf(var + LNEPS);
    }
    __syncthreads();
    float mean = red[half][0], rstd = red[half][1];
    sn[half][ht]       = fmaf((x0 - mean) * rstd, lnw[ht],       lnb[ht]);
    sn[half][ht + 128] = fmaf((x1 - mean) * rstd, lnw[ht + 128], lnb[ht + 128]);
    sn[half][ht + 256] = fmaf((x2 - mean) * rstd, lnw[ht + 256], lnb[ht + 256]);
    __syncthreads();

    float acc = 0.f;
#pragma unroll 8
    for (int c = 0; c < C_S; c++)
        acc = fmaf(sn[half][c], __ldg(Ws + (size_t)c * C_ATOM + ht), acc);
    g_u[(size_t)t * C_ATOM + ht] = acc;
}

// ---------------------------------------------------------------------------
// K4: plm_out[a,b,:] = plm[a,b,:] + y[tok[a],tok[b],:]   (the big stream)
// One thread per float4 (16 floats per (a,b) pair = 4 quads).
// ---------------------------------------------------------------------------
__global__ __launch_bounds__(256) void plm_kernel(
    const float* __restrict__ plm, float* __restrict__ out)
{
    int i = blockIdx.x * 256 + threadIdx.x;   // float4 index, 4,194,304 total
    int a = i >> 12;                          // 4096 float4 per atom-row
    int r = i & 4095;
    int b = r >> 2;
    int q = r & 3;
    int ta = g_tok[a];
    int tb = g_tok[b];

    float4 p  = __ldg((const float4*)plm + i);
    float4 yv = *((const float4*)g_y + (((ta << 8) + tb) << 2) + q);
    float4 o;
    o.x = p.x + yv.x; o.y = p.y + yv.y; o.z = p.z + yv.z; o.w = p.w + yv.w;
    ((float4*)out)[i] = o;
}

// ---------------------------------------------------------------------------
// K5: cl_out = cl + u[tok[a]] ;  ql_out = ql + rl @ W_r
// ---------------------------------------------------------------------------
__global__ __launch_bounds__(256) void clql_kernel(
    const float* __restrict__ cl, const float* __restrict__ ql,
    const float* __restrict__ rl, const float* __restrict__ Wr,
    float* __restrict__ out_cl, float* __restrict__ out_ql)
{
    int i = blockIdx.x * 256 + threadIdx.x;   // 131072
    int a = i >> 7, c = i & 127;
    out_cl[i] = cl[i] + g_u[(size_t)g_tok[a] * C_ATOM + c];
    float r0 = __ldg(rl + a * 3);
    float r1 = __ldg(rl + a * 3 + 1);
    float r2 = __ldg(rl + a * 3 + 2);
    out_ql[i] = ql[i] + fmaf(r0, Wr[c], fmaf(r1, Wr[128 + c], r2 * Wr[256 + c]));
}

// ---------------------------------------------------------------------------
extern "C" void kernel_launch(void* const* d_in, const int* in_sizes, int n_in,
                              void* d_out, int out_size)
{
    const float* a2t     = (const float*)d_in[0];
    const float* cl      = (const float*)d_in[1];
    const float* plm     = (const float*)d_in[2];
    const float* ql      = (const float*)d_in[3];
    const float* s_trunk = (const float*)d_in[4];
    const float* zij     = (const float*)d_in[5];
    const float* rl      = (const float*)d_in[6];
    const float* ln_s_w  = (const float*)d_in[7];
    const float* ln_s_b  = (const float*)d_in[8];
    const float* W_s     = (const float*)d_in[9];
    const float* ln_z_w  = (const float*)d_in[10];
    const float* ln_z_b  = (const float*)d_in[11];
    const float* W_z     = (const float*)d_in[12];
    const float* W_r     = (const float*)d_in[13];

    float* out_cl  = (float*)d_out;
    float* out_plm = out_cl + (size_t)N_ATOM * C_ATOM;
    float* out_ql  = out_plm + (size_t)N_ATOM * N_ATOM * C_PAIR;

    tok_kernel<<<N_ATOM / 8, 256>>>(a2t);
    y_kernel<<<512, 256>>>(zij, ln_z_w, ln_z_b, W_z);
    u_kernel<<<N_TOKEN / 2, 256>>>(s_trunk, ln_s_w, ln_s_b, W_s);
    plm_kernel<<<(N_ATOM * N_ATOM * C_PAIR / 4) / 256, 256>>>(plm, out_plm);
    clql_kernel<<<(N_ATOM * C_ATOM) / 256, 256>>>(cl, ql, rl, W_r, out_cl, out_ql);
}

// round 10
// speedup vs baseline: 1.0142x; 1.0142x over previous
#include <cuda_runtime.h>
#include <cstdint>

// Problem constants
#define N_ATOM   1024
#define N_TOKEN  256
#define C_S      384
#define C_Z      128
#define C_ATOM   128
#define C_PAIR   16
#define LNEPS    1e-5f

// Scratch (allocation-free rule: __device__ globals)
__device__ int   g_tok[N_ATOM];                       // atom -> token
__device__ float g_y[N_TOKEN * N_TOKEN * C_PAIR];     // 4 MB: LN_z(zij)@W_z per token pair
__device__ float g_u[N_TOKEN * C_ATOM];               // LN_s(s_trunk)@W_s per token

// ---------------------------------------------------------------------------
// K1: recover token index from one-hot rows (one warp per atom)
// ---------------------------------------------------------------------------
__global__ __launch_bounds__(256) void tok_kernel(const float* __restrict__ a2t)
{
    int a    = blockIdx.x * 8 + (threadIdx.x >> 5);
    int lane = threadIdx.x & 31;
    const float* row = a2t + (size_t)a * N_TOKEN;
    int best = 0;
#pragma unroll
    for (int i = 0; i < 8; i++) {
        int t = lane + 32 * i;
        if (row[t] > 0.5f) best = t;
    }
#pragma unroll
    for (int o = 16; o; o >>= 1)
        best = max(best, __shfl_xor_sync(0xffffffffu, best, o));
    if (lane == 0) g_tok[a] = best;
}

// ---------------------------------------------------------------------------
// K2: y[t,m,k] = (LN(zij[t,m,:]) ) @ W_z      (one warp per (t,m) pair)
// Each lane owns 4 channels; W_z rows for those channels live in registers
// (64 regs), so no per-pair smem/W_z re-read. 16-output cross-lane reduction
// via a 4-stage butterfly (15 shfl) + 1 redundancy-fold shfl.
// ---------------------------------------------------------------------------
__global__ __launch_bounds__(256, 2) void y_kernel(
    const float* __restrict__ zij, const float* __restrict__ lnw,
    const float* __restrict__ lnb, const float* __restrict__ Wz)
{
    __shared__ float s_Wz[C_Z * C_PAIR];   // 8 KB, staged once per block
    int tid = threadIdx.x;
    for (int i = tid; i < C_Z * C_PAIR; i += 256) s_Wz[i] = Wz[i];
    __syncthreads();

    int lane = tid & 31;
    int c0   = lane << 2;                  // this lane's first channel

    float wreg[4][16];
#pragma unroll
    for (int j = 0; j < 4; j++)
#pragma unroll
        for (int k = 0; k < 16; k++)
            wreg[j][k] = s_Wz[(c0 + j) * 16 + k];

    float lw0 = lnw[c0], lw1 = lnw[c0 + 1], lw2 = lnw[c0 + 2], lw3 = lnw[c0 + 3];
    float lb0 = lnb[c0], lb1 = lnb[c0 + 1], lb2 = lnb[c0 + 2], lb3 = lnb[c0 + 3];

    int gw = blockIdx.x * 8 + (tid >> 5);
    int nw = gridDim.x * 8;
    const float4* z4 = (const float4*)zij;

    for (int pair = gw; pair < N_TOKEN * N_TOKEN; pair += nw) {
        float4 z = __ldg(z4 + (size_t)pair * 32 + lane);

        float s  = z.x + z.y + z.z + z.w;
        float ss = fmaf(z.x, z.x, fmaf(z.y, z.y, fmaf(z.z, z.z, z.w * z.w)));
#pragma unroll
        for (int o = 16; o; o >>= 1) {
            s  += __shfl_xor_sync(0xffffffffu, s,  o);
            ss += __shfl_xor_sync(0xffffffffu, ss, o);
        }
        float mean = s * (1.0f / 128.0f);
        float var  = ss * (1.0f / 128.0f) - mean * mean;
        float rstd = rsqrtf(var + LNEPS);

        float n0 = fmaf((z.x - mean) * rstd, lw0, lb0);
        float n1 = fmaf((z.y - mean) * rstd, lw1, lb1);
        float n2 = fmaf((z.z - mean) * rstd, lw2, lb2);
        float n3 = fmaf((z.w - mean) * rstd, lw3, lb3);

        float acc[16];
#pragma unroll
        for (int k = 0; k < 16; k++)
            acc[k] = fmaf(n0, wreg[0][k],
                     fmaf(n1, wreg[1][k],
                     fmaf(n2, wreg[2][k], n3 * wreg[3][k])));

        // 16-value butterfly reduction across 32 lanes.
        // After stage with mask m=16>>st, k-bit (3-st) == lane bit (4-st).
#pragma unroll
        for (int st = 0; st < 4; st++) {
            const int m = 16 >> st;
            const int h = 8 >> st;
            bool up = (lane & m) != 0;
#pragma unroll
            for (int j = 0; j < h; j++) {
                float send = up ? acc[j] : acc[j + h];
                float keep = up ? acc[j + h] : acc[j];
                acc[j] = keep + __shfl_xor_sync(0xffffffffu, send, m);
            }
        }
        acc[0] += __shfl_xor_sync(0xffffffffu, acc[0], 1);   // fold lane-bit0 redundancy
        int k = (lane >> 1) & 15;
        if ((lane & 1) == 0)
            g_y[(size_t)pair * C_PAIR + k] = acc[0];
    }
}

// ---------------------------------------------------------------------------
// K3: u[t,:] = LN(s_trunk[t,:]) @ W_s   (2 tokens per 256-thread block)
// ---------------------------------------------------------------------------
__global__ __launch_bounds__(256) void u_kernel(
    const float* __restrict__ s_trunk, const float* __restrict__ lnw,
    const float* __restrict__ lnb, const float* __restrict__ Ws)
{
    __shared__ float sn[2][C_S];
    __shared__ float wred[8][2];
    __shared__ float red[2][2];

    int tid  = threadIdx.x;
    int half = tid >> 7;          // 0/1: which token this half handles
    int ht   = tid & 127;
    int t    = blockIdx.x * 2 + half;

    const float* sr = s_trunk + (size_t)t * C_S;
    float x0 = sr[ht], x1 = sr[ht + 128], x2 = sr[ht + 256];
    float s  = x0 + x1 + x2;
    float ss = fmaf(x0, x0, fmaf(x1, x1, x2 * x2));
#pragma unroll
    for (int o = 16; o; o >>= 1) {
        s  += __shfl_xor_sync(0xffffffffu, s,  o);
        ss += __shfl_xor_sync(0xffffffffu, ss, o);
    }
    int warp = tid >> 5, lane = tid & 31;
    if (lane == 0) { wred[warp][0] = s; wred[warp][1] = ss; }
    __syncthreads();
    if (ht == 0) {
        float S = 0.f, SS = 0.f;
        for (int w = half * 4; w < half * 4 + 4; w++) { S += wred[w][0]; SS += wred[w][1]; }
        float mean = S * (1.0f / 384.0f);
        float var  = SS * (1.0f / 384.0f) - mean * mean;
        red[half][0] = mean;
        red[half][1] = rsqrtf(var + LNEPS);
    }
    __syncthreads();
    float mean = red[half][0], rstd = red[half][1];
    sn[half][ht]       = fmaf((x0 - mean) * rstd, lnw[ht],       lnb[ht]);
    sn[half][ht + 128] = fmaf((x1 - mean) * rstd, lnw[ht + 128], lnb[ht + 128]);
    sn[half][ht + 256] = fmaf((x2 - mean) * rstd, lnw[ht + 256], lnb[ht + 256]);
    __syncthreads();

    float acc = 0.f;
#pragma unroll 8
    for (int c = 0; c < C_S; c++)
        acc = fmaf(sn[half][c], __ldg(Ws + (size_t)c * C_ATOM + ht), acc);
    g_u[(size_t)t * C_ATOM + ht] = acc;
}

// ---------------------------------------------------------------------------
// K4: plm_out[a,b,:] = plm[a,b,:] + y[tok[a],tok[b],:]   (the big stream)
// One thread per float4 (16 floats per (a,b) pair = 4 quads).
// ---------------------------------------------------------------------------
__global__ __launch_bounds__(256) void plm_kernel(
    const float* __restrict__ plm, float* __restrict__ out)
{
    int i = blockIdx.x * 256 + threadIdx.x;   // float4 index, 4,194,304 total
    int a = i >> 12;                          // 4096 float4 per atom-row
    int r = i & 4095;
    int b = r >> 2;
    int q = r & 3;
    int ta = g_tok[a];
    int tb = g_tok[b];

    float4 p  = __ldg((const float4*)plm + i);
    float4 yv = *((const float4*)g_y + (((ta << 8) + tb) << 2) + q);
    float4 o;
    o.x = p.x + yv.x; o.y = p.y + yv.y; o.z = p.z + yv.z; o.w = p.w + yv.w;
    ((float4*)out)[i] = o;
}

// ---------------------------------------------------------------------------
// K5: cl_out = cl + u[tok[a]] ;  ql_out = ql + rl @ W_r
// ---------------------------------------------------------------------------
__global__ __launch_bounds__(256) void clql_kernel(
    const float* __restrict__ cl, const float* __restrict__ ql,
    const float* __restrict__ rl, const float* __restrict__ Wr,
    float* __restrict__ out_cl, float* __restrict__ out_ql)
{
    int i = blockIdx.x * 256 + threadIdx.x;   // 131072
    int a = i >> 7, c = i & 127;
    out_cl[i] = cl[i] + g_u[(size_t)g_tok[a] * C_ATOM + c];
    float r0 = __ldg(rl + a * 3);
    float r1 = __ldg(rl + a * 3 + 1);
    float r2 = __ldg(rl + a * 3 + 2);
    out_ql[i] = ql[i] + fmaf(r0, Wr[c], fmaf(r1, Wr[128 + c], r2 * Wr[256 + c]));
}

// ---------------------------------------------------------------------------
extern "C" void kernel_launch(void* const* d_in, const int* in_sizes, int n_in,
                              void* d_out, int out_size)
{
    const float* a2t     = (const float*)d_in[0];
    const float* cl      = (const float*)d_in[1];
    const float* plm     = (const float*)d_in[2];
    const float* ql      = (const float*)d_in[3];
    const float* s_trunk = (const float*)d_in[4];
    const float* zij     = (const float*)d_in[5];
    const float* rl      = (const float*)d_in[6];
    const float* ln_s_w  = (const float*)d_in[7];
    const float* ln_s_b  = (const float*)d_in[8];
    const float* W_s     = (const float*)d_in[9];
    const float* ln_z_w  = (const float*)d_in[10];
    const float* ln_z_b  = (const float*)d_in[11];
    const float* W_z     = (const float*)d_in[12];
    const float* W_r     = (const float*)d_in[13];

    float* out_cl  = (float*)d_out;
    float* out_plm = out_cl + (size_t)N_ATOM * C_ATOM;
    float* out_ql  = out_plm + (size_t)N_ATOM * N_ATOM * C_PAIR;

    tok_kernel<<<N_ATOM / 8, 256>>>(a2t);
    y_kernel<<<512, 256>>>(zij, ln_z_w, ln_z_b, W_z);
    u_kernel<<<N_TOKEN / 2, 256>>>(s_trunk, ln_s_w, ln_s_b, W_s);
    plm_kernel<<<(N_ATOM * N_ATOM * C_PAIR / 4) / 256, 256>>>(plm, out_plm);
    clql_kernel<<<(N_ATOM * C_ATOM) / 256, 256>>>(cl, ql, rl, W_r, out_cl, out_ql);
}